// round 16
// baseline (speedup 1.0000x reference)
#include <cuda_runtime.h>
#include <cuda_fp16.h>
#include <cstdint>

// ============================ problem constants ============================
#define NROWS   8192
#define BHALF   4096
#define DIM     256
#define TM      128
#define TN      128
#define INV_T   14.2857142857142857f      // 1/0.07
#define K2      20.609929155556620f       // log2(e)/0.07  (for ex2)

#define NCTA    148
// weighted circulant triangle: diag tile weight 5, off-diag weight 6
#define W_DIAG  5
#define W_OFF   6
#define TOTW    12416
#define WBASE32 6304        // 32*197

// SMEM tile: 128 rows x (256 fp16 + 8 pad) = 528 B/row -> conflict-free ldmatrix
#define ROW_B   528
#define TILEB   (128 * ROW_B)      // 67584
#define OFF_A   2048               // labs[3][128] ints live at offset 0
#define OFF_B0  (OFF_A + TILEB)    // 69632
#define OFF_B1  (OFF_B0 + TILEB)   // 137216
#define SMEM_BYTES (OFF_B1 + TILEB) // 204800

// ============================ device scratch ============================
__device__ __half g_Z[NROWS * DIM];    // normalized rows, fp16
__device__ int   g_lab[NROWS];
__device__ float g_pos[NROWS];
__device__ float g_se[NROWS];
__device__ int   g_done;

// ============================ PTX helpers (baseline features only) ============================
__device__ __forceinline__ uint32_t smem_to_u32(const void* p) {
    uint32_t a;
    asm("{ .reg .u64 t; cvta.to.shared.u64 t, %1; cvt.u32.u64 %0, t; }" : "=r"(a) : "l"(p));
    return a;
}
__device__ __forceinline__ float ex2f(float x) {
    float y; asm("ex2.approx.f32 %0, %1;" : "=f"(y) : "f"(x)); return y;
}

#define LDSM_X4(r0, r1, r2, r3, addr) \
    asm volatile("ldmatrix.sync.aligned.m8n8.x4.shared.b16 {%0,%1,%2,%3}, [%4];" \
        : "=r"(r0), "=r"(r1), "=r"(r2), "=r"(r3) : "r"(addr))

// f16 accumulators (perf-neutral vs f32-acc on this chip; halves accumulator regs)
#define MMA16816F16(c, a, b0, b1) \
    asm volatile("mma.sync.aligned.m16n8k16.row.col.f16.f16.f16.f16 " \
        "{%0,%1}, {%2,%3,%4,%5}, {%6,%7}, {%0,%1};" \
        : "+r"((c)[0]), "+r"((c)[1]) \
        : "r"((a)[0]), "r"((a)[1]), "r"((a)[2]), "r"((a)[3]), "r"(b0), "r"(b1))

#define CP_ASYNC16(dst_u32, src_ptr) \
    asm volatile("cp.async.cg.shared.global [%0], [%1], 16;" :: "r"(dst_u32), "l"(src_ptr))
#define CP_COMMIT() asm volatile("cp.async.commit_group;" ::: "memory")
#define CP_WAIT0()  asm volatile("cp.async.wait_group 0;" ::: "memory")

__device__ __forceinline__ int dmax_of(int ib) { return (ib < 32) ? 32 : 31; }

// locate first tile (ib, d) whose start-weight sw >= w
__device__ __forceinline__ void locate_w(int w, int& ib, int& d, int& sw) {
    int r;
    if (w < WBASE32) { ib = w / 197; r = w - ib * 197; }
    else { int x = w - WBASE32; ib = 32 + x / 191; r = x - (ib - 32) * 191; }
    int base = w - r;
    if (r < W_DIAG) { d = 0; sw = base; }
    else { d = 1 + (r - W_DIAG) / W_OFF; sw = base + W_DIAG + W_OFF * (d - 1); }
    if (sw < w) {
        sw += (d == 0) ? W_DIAG : W_OFF;
        d++;
        if (d > dmax_of(ib)) { ib++; d = 0; }
    }
}

// ============================ kernel 1: normalize + fp16 + labels + init ============================
// One warp per row, 8 rows per block, 1024 blocks.
__global__ void __launch_bounds__(256) k_norm(const float* __restrict__ zi, const float* __restrict__ zj,
                       const int* __restrict__ lab32) {
    __shared__ int stride_sh;
    if (threadIdx.x < 32) {
        // stride detect in ONE parallel load round: int64 storage has all-zero odd words
        int v = lab32[2 * threadIdx.x + 1];
        unsigned m = __ballot_sync(0xffffffffu, v != 0);
        if (threadIdx.x == 0) {
            stride_sh = m ? 1 : 2;
            if (blockIdx.x == 0) g_done = 0;
        }
    }
    int w    = threadIdx.x >> 5;
    int lane = threadIdx.x & 31;
    int row  = blockIdx.x * 8 + w;
    const float4* src = reinterpret_cast<const float4*>(
        (row < BHALF) ? (zi + (size_t)row * DIM) : (zj + (size_t)(row - BHALF) * DIM));
    float4 u0 = src[lane];
    float4 u1 = src[lane + 32];
    float ss = u0.x*u0.x + u0.y*u0.y + u0.z*u0.z + u0.w*u0.w
             + u1.x*u1.x + u1.y*u1.y + u1.z*u1.z + u1.w*u1.w;
#pragma unroll
    for (int o = 16; o > 0; o >>= 1) ss += __shfl_xor_sync(0xffffffffu, ss, o);
    float inv = 1.f / fmaxf(sqrtf(ss), 1e-12f);
    __half2 h0[2], h1[2];
    h0[0] = __floats2half2_rn(u0.x * inv, u0.y * inv);
    h0[1] = __floats2half2_rn(u0.z * inv, u0.w * inv);
    h1[0] = __floats2half2_rn(u1.x * inv, u1.y * inv);
    h1[1] = __floats2half2_rn(u1.z * inv, u1.w * inv);
    __half* dst = g_Z + (size_t)row * DIM;
    *reinterpret_cast<uint2*>(dst + lane * 4)        = *reinterpret_cast<uint2*>(h0);
    *reinterpret_cast<uint2*>(dst + (lane + 32) * 4) = *reinterpret_cast<uint2*>(h1);
    __syncthreads();
    if (lane == 0) {
        g_lab[row] = lab32[(row & (BHALF - 1)) * stride_sh];
        g_pos[row] = 0.f;
        g_se[row]  = 0.f;
    }
}

// ============================ kernel 2: pipelined symmetric GEMM + last-CTA final ============================
__device__ __forceinline__ void cpasync_tile(uint32_t dst, const __half* src, int tid) {
#pragma unroll
    for (int it = 0; it < 8; it++) {
        int idx = tid + it * 512;        // 0..4095 16B-chunks
        int row = idx >> 5, c = idx & 31;
        const char* s = reinterpret_cast<const char*>(src) + row * 512 + c * 16;
        CP_ASYNC16(dst + row * ROW_B + c * 16, s);
    }
}

// Column-group epilogue for the PREVIOUS off-diagonal tile (f16x2 accumulators).
__device__ __forceinline__ void epi_group(
    int ci, const uint32_t cprev[2][4][2], const int* lb_prev, const int lab_row[4],
    float pos[4], float se[4], int jb_prev, int wn, int lane)
{
    int nt = ci >> 1, q = ci & 1;
    int labc = lb_prev[wn + nt * 8 + (lane & 3) * 2 + q];
    float cp = 0.f, ce = 0.f;
#pragma unroll
    for (int mt = 0; mt < 2; mt++)
#pragma unroll
        for (int h = 0; h < 2; h++) {
            int s = mt * 2 + h;
            float2 f = __half22float2(*reinterpret_cast<const __half2*>(&cprev[mt][nt][h]));
            float v = q ? f.y : f.x;
            if (labc == lab_row[s]) { pos[s] += v; cp += v; }
            else { float e = ex2f(v * K2); se[s] += e; ce += e; }
        }
    cp += __shfl_xor_sync(0xffffffffu, cp, 4);
    cp += __shfl_xor_sync(0xffffffffu, cp, 8);
    cp += __shfl_xor_sync(0xffffffffu, cp, 16);
    ce += __shfl_xor_sync(0xffffffffu, ce, 4);
    ce += __shfl_xor_sync(0xffffffffu, ce, 8);
    ce += __shfl_xor_sync(0xffffffffu, ce, 16);
    if (lane < 4) {
        int col = wn + nt * 8 + lane * 2 + q;
        atomicAdd(&g_pos[jb_prev * TN + col], cp * INV_T);
        atomicAdd(&g_se[jb_prev * TN + col],  ce);
    }
}

// GEMM with software-pipelined fragment loads; optionally interleaves previous-tile epilogue.
template <bool FUSE>
__device__ __forceinline__ void gemm_tile(
    uint32_t aBase, uint32_t bBase, int lane,
    uint32_t c[2][4][2],
    const uint32_t cprev[2][4][2], const int* lb_prev, const int lab_row[4],
    float pos[4], float se[4], int jb_prev, int wn)
{
#pragma unroll
    for (int mt = 0; mt < 2; mt++)
#pragma unroll
        for (int nt = 0; nt < 4; nt++) { c[mt][nt][0] = 0u; c[mt][nt][1] = 0u; }

    const int rsel = (lane & 15);
    const int koff = ((lane >> 4) << 3) * 2;

    uint32_t a[2][2][4], b[2][2][4];   // [buf][frag][reg]
    {
        int kb = koff;
        LDSM_X4(a[0][0][0], a[0][0][1], a[0][0][2], a[0][0][3], aBase + rsel * ROW_B + kb);
        LDSM_X4(a[0][1][0], a[0][1][1], a[0][1][2], a[0][1][3], aBase + (16 + rsel) * ROW_B + kb);
        LDSM_X4(b[0][0][0], b[0][0][1], b[0][0][2], b[0][0][3], bBase + rsel * ROW_B + kb);
        LDSM_X4(b[0][1][0], b[0][1][1], b[0][1][2], b[0][1][3], bBase + (16 + rsel) * ROW_B + kb);
    }

#pragma unroll
    for (int kk = 0; kk < 16; kk++) {
        int cur = kk & 1, nxt = cur ^ 1;
        if (kk < 15) {
            int kb = (kk + 1) * 32 + koff;
            LDSM_X4(a[nxt][0][0], a[nxt][0][1], a[nxt][0][2], a[nxt][0][3], aBase + rsel * ROW_B + kb);
            LDSM_X4(a[nxt][1][0], a[nxt][1][1], a[nxt][1][2], a[nxt][1][3], aBase + (16 + rsel) * ROW_B + kb);
            LDSM_X4(b[nxt][0][0], b[nxt][0][1], b[nxt][0][2], b[nxt][0][3], bBase + rsel * ROW_B + kb);
            LDSM_X4(b[nxt][1][0], b[nxt][1][1], b[nxt][1][2], b[nxt][1][3], bBase + (16 + rsel) * ROW_B + kb);
        }
#pragma unroll
        for (int mt = 0; mt < 2; mt++)
#pragma unroll
            for (int nt = 0; nt < 4; nt++)
                MMA16816F16(c[mt][nt], a[cur][mt],
                            b[cur][nt >> 1][nt & 1], b[cur][nt >> 1][2 + (nt & 1)]);

        if (FUSE && (kk & 1))
            epi_group(kk >> 1, cprev, lb_prev, lab_row, pos, se, jb_prev, wn, lane);
    }
}

__global__ void __launch_bounds__(512, 1) k_sim(float* __restrict__ out) {
    extern __shared__ char smem[];
    uint32_t su = smem_to_u32(smem);
    int* labs = reinterpret_cast<int*>(smem);     // [3][128] triple-buffered labels

    int tid  = threadIdx.x;
    int lane = tid & 31;
    int wid  = tid >> 5;                 // 0..15
    const int wm = (wid >> 2) * 32;      // warp m-offset
    const int wn = (wid & 3) * 32;       // warp n-offset
    const int g  = lane >> 2;
    const int t4 = lane & 3;

    int w0 = (blockIdx.x * TOTW) / NCTA;
    int w1 = ((blockIdx.x + 1) * TOTW) / NCTA;
    int ib, d, sw;
    locate_w(w0, ib, d, sw);
    // NOTE: every CTA has work (w1-w0 ~ 84 > max tile weight 6) -> no early return needed.

    // pre-loop: prefetch first tile's B + labels into buf 0 / slot 0
    {
        int jb0 = (ib + d) & 63;
        if (d != 0) cpasync_tile(su + OFF_B0, g_Z + (size_t)jb0 * TN * DIM, tid);
        CP_COMMIT();
        if (tid < 128) labs[tid] = g_lab[jb0 * TN + tid];
    }
    int buf = 0, slot = 0;

    int cur_ib = -1;
    int lab_row[4], row_g[4];
    float pos[4], se[4];

    bool     pending = false;
    uint32_t cprev[2][4][2];
    int      jb_prev = 0, slot_prev = 0;
    uint32_t c[2][4][2];

    while (true) {
        int jb = (ib + d) & 63;

        if (ib != cur_ib) {
            if (pending) {
#pragma unroll
                for (int ci = 0; ci < 8; ci++)
                    epi_group(ci, cprev, labs + slot_prev * 128, lab_row, pos, se, jb_prev, wn, lane);
                pending = false;
            }
            if (cur_ib >= 0) {
#pragma unroll
                for (int s = 0; s < 4; s++) {
                    float p = pos[s], e = se[s];
                    p += __shfl_xor_sync(0xffffffffu, p, 1);
                    p += __shfl_xor_sync(0xffffffffu, p, 2);
                    e += __shfl_xor_sync(0xffffffffu, e, 1);
                    e += __shfl_xor_sync(0xffffffffu, e, 2);
                    if (t4 == 0) {
                        atomicAdd(&g_pos[row_g[s]], p * INV_T);
                        atomicAdd(&g_se[row_g[s]],  e);
                    }
                }
            }
            cpasync_tile(su + OFF_A, g_Z + (size_t)ib * TM * DIM, tid);
            CP_COMMIT();
            CP_WAIT0();            // also drains any in-flight B prefetch
            __syncthreads();
            cur_ib = ib;
#pragma unroll
            for (int s = 0; s < 4; s++) {
                int mt = s >> 1, h = s & 1;
                row_g[s]   = ib * TM + wm + mt * 16 + g + 8 * h;
                lab_row[s] = g_lab[row_g[s]];
                pos[s] = 0.f;  se[s] = 0.f;
            }
        }

        uint32_t bbuf = (d == 0) ? (su + OFF_A) : (su + (buf ? OFF_B1 : OFF_B0));

        int swn = sw + ((d == 0) ? W_DIAG : W_OFF);
        int ibn = ib, dn = d + 1;
        if (dn > dmax_of(ib)) { ibn++; dn = 0; }
        bool has_next = (ibn < 64) && (swn < w1);
        int slot_next = (slot == 2) ? 0 : slot + 1;

        if (has_next) {
            int jn = (ibn + dn) & 63;
            if (dn != 0) cpasync_tile(su + ((buf ^ 1) ? OFF_B1 : OFF_B0),
                                      g_Z + (size_t)jn * TN * DIM, tid);
            CP_COMMIT();
            if (tid < 128) labs[slot_next * 128 + tid] = g_lab[jn * TN + tid];
        }

        uint32_t aBase = su + OFF_A + wm * ROW_B;
        uint32_t bBase = bbuf + wn * ROW_B;
        const int* lb = labs + slot * 128;

        if (d == 0) {
            gemm_tile<false>(aBase, bBase, lane, c, cprev, lb, lab_row, pos, se, jb_prev, wn);
#pragma unroll
            for (int mt = 0; mt < 2; mt++)
#pragma unroll
                for (int nt = 0; nt < 4; nt++)
#pragma unroll
                    for (int h = 0; h < 2; h++) {
                        int s = mt * 2 + h;
                        float2 f = __half22float2(*reinterpret_cast<__half2*>(&c[mt][nt][h]));
#pragma unroll
                        for (int q = 0; q < 2; q++) {
                            int coll = wn + nt * 8 + t4 * 2 + q;
                            float v  = q ? f.y : f.x;
                            if (lb[coll] == lab_row[s]) {
                                if (ib * TM + coll != row_g[s]) pos[s] += v;
                            } else {
                                se[s] += ex2f(v * K2);
                            }
                        }
                    }
        } else {
            if (pending)
                gemm_tile<true>(aBase, bBase, lane, c, cprev, labs + slot_prev * 128,
                                lab_row, pos, se, jb_prev, wn);
            else
                gemm_tile<false>(aBase, bBase, lane, c, cprev, lb, lab_row, pos, se, jb_prev, wn);

#pragma unroll
            for (int mt = 0; mt < 2; mt++)
#pragma unroll
                for (int nt = 0; nt < 4; nt++) {
                    cprev[mt][nt][0] = c[mt][nt][0];
                    cprev[mt][nt][1] = c[mt][nt][1];
                }
            jb_prev   = jb;
            slot_prev = slot;
            pending   = true;
        }

        if (!has_next) break;
        CP_WAIT0();
        __syncthreads();
        ib = ibn; d = dn; sw = swn; buf ^= 1; slot = slot_next;
    }

    if (pending) {
#pragma unroll
        for (int ci = 0; ci < 8; ci++)
            epi_group(ci, cprev, labs + slot_prev * 128, lab_row, pos, se, jb_prev, wn, lane);
    }
#pragma unroll
    for (int s = 0; s < 4; s++) {
        float p = pos[s], e = se[s];
        p += __shfl_xor_sync(0xffffffffu, p, 1);
        p += __shfl_xor_sync(0xffffffffu, p, 2);
        e += __shfl_xor_sync(0xffffffffu, e, 1);
        e += __shfl_xor_sync(0xffffffffu, e, 2);
        if (t4 == 0) {
            atomicAdd(&g_pos[row_g[s]], p * INV_T);
            atomicAdd(&g_se[row_g[s]],  e);
        }
    }

    // ---- fused final reduction: last CTA to arrive computes the loss ----
    __shared__ int is_last;
    __threadfence();                 // make this CTA's atomics globally visible
    __syncthreads();                 // all threads of CTA fenced
    if (tid == 0) {
        int old = atomicAdd(&g_done, 1);
        is_last = (old == NCTA - 1);
    }
    __syncthreads();
    if (is_last) {
        __threadfence();             // acquire: see all other CTAs' atomics
        float* red = reinterpret_cast<float*>(smem);   // reuse label scratch
        float acc = 0.f;
        for (int r = tid; r < NROWS; r += 512) {
            // loss_i = logaddexp(0, lse_neg - pos_sim); |sim|<=14.3 so sum-exp is fp32-safe
            float x = logf(g_se[r]) - g_pos[r];
            acc += (x > 0.f) ? (x + log1pf(expf(-x))) : log1pf(expf(x));
        }
#pragma unroll
        for (int o = 16; o > 0; o >>= 1) acc += __shfl_xor_sync(0xffffffffu, acc, o);
        if (lane == 0) red[wid] = acc;
        __syncthreads();
        if (tid < 32) {
            float a = (tid < 16) ? red[tid] : 0.f;
#pragma unroll
            for (int o = 8; o > 0; o >>= 1) a += __shfl_xor_sync(0xffffffffu, a, o);
            if (tid == 0) out[0] = a * (1.0f / (float)NROWS);
        }
    }
}

// ============================ launch ============================
extern "C" void kernel_launch(void* const* d_in, const int* in_sizes, int n_in,
                              void* d_out, int out_size) {
    (void)in_sizes; (void)n_in; (void)out_size;
    const float* zi  = (const float*)d_in[0];
    const float* zj  = (const float*)d_in[1];
    const int*   lab = (const int*)d_in[2];    // int32 or int64; auto-detected

    cudaFuncSetAttribute(k_sim, cudaFuncAttributeMaxDynamicSharedMemorySize, SMEM_BYTES);

    k_norm<<<NROWS / 8, 256>>>(zi, zj, lab);
    k_sim<<<NCTA, 512, SMEM_BYTES>>>((float*)d_out);
}

// round 17
// speedup vs baseline: 1.0854x; 1.0854x over previous
#include <cuda_runtime.h>
#include <cuda_fp16.h>
#include <cstdint>

// ============================ problem constants ============================
#define NROWS   8192
#define BHALF   4096
#define DIM     256
#define TM      128
#define TN      128
#define INV_T   14.2857142857142857f      // 1/0.07
#define K2      20.609929155556620f       // log2(e)/0.07  (for ex2)

#define NCTA    148
// weighted circulant triangle: diag tile weight 5, off-diag weight 6
#define W_DIAG  5
#define W_OFF   6
#define TOTW    12416
#define WBASE32 6304        // 32*197

// SMEM tile: 128 rows x (256 fp16 + 8 pad) = 528 B/row -> conflict-free ldmatrix
#define ROW_B   528
#define TILEB   (128 * ROW_B)      // 67584
#define OFF_A   2048               // labs[3][128] ints live at offset 0
#define OFF_B0  (OFF_A + TILEB)    // 69632
#define OFF_B1  (OFF_B0 + TILEB)   // 137216
#define SMEM_BYTES (OFF_B1 + TILEB) // 204800

// ============================ device scratch ============================
__device__ __half g_Z[NROWS * DIM];    // normalized rows, fp16
__device__ int   g_lab[NROWS];
__device__ float g_pos[NROWS];
__device__ float g_se[NROWS];

// ============================ PTX helpers (baseline features only) ============================
__device__ __forceinline__ uint32_t smem_to_u32(const void* p) {
    uint32_t a;
    asm("{ .reg .u64 t; cvta.to.shared.u64 t, %1; cvt.u32.u64 %0, t; }" : "=r"(a) : "l"(p));
    return a;
}
__device__ __forceinline__ float ex2f(float x) {
    float y; asm("ex2.approx.f32 %0, %1;" : "=f"(y) : "f"(x)); return y;
}

#define LDSM_X4(r0, r1, r2, r3, addr) \
    asm volatile("ldmatrix.sync.aligned.m8n8.x4.shared.b16 {%0,%1,%2,%3}, [%4];" \
        : "=r"(r0), "=r"(r1), "=r"(r2), "=r"(r3) : "r"(addr))

// f16 accumulators (perf-neutral vs f32-acc on this chip; halves accumulator regs)
#define MMA16816F16(c, a, b0, b1) \
    asm volatile("mma.sync.aligned.m16n8k16.row.col.f16.f16.f16.f16 " \
        "{%0,%1}, {%2,%3,%4,%5}, {%6,%7}, {%0,%1};" \
        : "+r"((c)[0]), "+r"((c)[1]) \
        : "r"((a)[0]), "r"((a)[1]), "r"((a)[2]), "r"((a)[3]), "r"(b0), "r"(b1))

#define CP_ASYNC16(dst_u32, src_ptr) \
    asm volatile("cp.async.cg.shared.global [%0], [%1], 16;" :: "r"(dst_u32), "l"(src_ptr))
#define CP_COMMIT() asm volatile("cp.async.commit_group;" ::: "memory")
#define CP_WAIT0()  asm volatile("cp.async.wait_group 0;" ::: "memory")

__device__ __forceinline__ int dmax_of(int ib) { return (ib < 32) ? 32 : 31; }

// locate first tile (ib, d) whose start-weight sw >= w
__device__ __forceinline__ void locate_w(int w, int& ib, int& d, int& sw) {
    int r;
    if (w < WBASE32) { ib = w / 197; r = w - ib * 197; }
    else { int x = w - WBASE32; ib = 32 + x / 191; r = x - (ib - 32) * 191; }
    int base = w - r;
    if (r < W_DIAG) { d = 0; sw = base; }
    else { d = 1 + (r - W_DIAG) / W_OFF; sw = base + W_DIAG + W_OFF * (d - 1); }
    if (sw < w) {
        sw += (d == 0) ? W_DIAG : W_OFF;
        d++;
        if (d > dmax_of(ib)) { ib++; d = 0; }
    }
}

// ============================ kernel 1: normalize + fp16 + labels + init ============================
// half-warp per row: 16 lanes x 4 float4 = 256 floats, MLP=4 per thread
__global__ void __launch_bounds__(256) k_norm(const float* __restrict__ zi, const float* __restrict__ zj,
                       const int* __restrict__ lab32, float* __restrict__ out) {
    __shared__ int stride_sh;
    if (threadIdx.x < 32) {
        // stride detect in ONE parallel load round: int64 storage has all-zero odd words
        int v = lab32[2 * threadIdx.x + 1];
        unsigned m = __ballot_sync(0xffffffffu, v != 0);
        if (threadIdx.x == 0) {
            stride_sh = m ? 1 : 2;
            if (blockIdx.x == 0) out[0] = 0.f;
        }
    }
    int half = threadIdx.x >> 4;           // 0..15 half-warps
    int hl   = threadIdx.x & 15;           // lane in half-warp
    int row  = blockIdx.x * 16 + half;
    const float4* src = reinterpret_cast<const float4*>(
        (row < BHALF) ? (zi + (size_t)row * DIM) : (zj + (size_t)(row - BHALF) * DIM));
    float4 u[4];
#pragma unroll
    for (int i = 0; i < 4; i++) u[i] = src[hl + 16 * i];
    float ss = 0.f;
#pragma unroll
    for (int i = 0; i < 4; i++) ss += u[i].x*u[i].x + u[i].y*u[i].y + u[i].z*u[i].z + u[i].w*u[i].w;
#pragma unroll
    for (int o = 8; o > 0; o >>= 1) ss += __shfl_xor_sync(0xffffffffu, ss, o);
    float inv = 1.f / fmaxf(sqrtf(ss), 1e-12f);
#pragma unroll
    for (int i = 0; i < 4; i++) {
        __half2 h2[2];
        h2[0] = __floats2half2_rn(u[i].x * inv, u[i].y * inv);
        h2[1] = __floats2half2_rn(u[i].z * inv, u[i].w * inv);
        *reinterpret_cast<uint2*>(g_Z + (size_t)row * DIM + (hl + 16 * i) * 4) =
            *reinterpret_cast<uint2*>(h2);
    }
    __syncthreads();
    if (hl == 0) {
        g_lab[row] = lab32[(row & (BHALF - 1)) * stride_sh];
        g_pos[row] = 0.f;
        g_se[row]  = 0.f;
    }
}

// ============================ kernel 2: pipelined symmetric GEMM ============================
__device__ __forceinline__ void cpasync_tile(uint32_t dst, const __half* src, int tid) {
#pragma unroll
    for (int it = 0; it < 8; it++) {
        int idx = tid + it * 512;        // 0..4095 16B-chunks
        int row = idx >> 5, c = idx & 31;
        const char* s = reinterpret_cast<const char*>(src) + row * 512 + c * 16;
        CP_ASYNC16(dst + row * ROW_B + c * 16, s);
    }
}

// Column-group epilogue for the PREVIOUS off-diagonal tile (f16x2 accumulators).
__device__ __forceinline__ void epi_group(
    int ci, const uint32_t cprev[2][4][2], const int* lb_prev, const int lab_row[4],
    float pos[4], float se[4], int jb_prev, int wn, int lane)
{
    int nt = ci >> 1, q = ci & 1;
    int labc = lb_prev[wn + nt * 8 + (lane & 3) * 2 + q];
    float cp = 0.f, ce = 0.f;
#pragma unroll
    for (int mt = 0; mt < 2; mt++)
#pragma unroll
        for (int h = 0; h < 2; h++) {
            int s = mt * 2 + h;
            float2 f = __half22float2(*reinterpret_cast<const __half2*>(&cprev[mt][nt][h]));
            float v = q ? f.y : f.x;
            if (labc == lab_row[s]) { pos[s] += v; cp += v; }
            else { float e = ex2f(v * K2); se[s] += e; ce += e; }
        }
    cp += __shfl_xor_sync(0xffffffffu, cp, 4);
    cp += __shfl_xor_sync(0xffffffffu, cp, 8);
    cp += __shfl_xor_sync(0xffffffffu, cp, 16);
    ce += __shfl_xor_sync(0xffffffffu, ce, 4);
    ce += __shfl_xor_sync(0xffffffffu, ce, 8);
    ce += __shfl_xor_sync(0xffffffffu, ce, 16);
    if (lane < 4) {
        int col = wn + nt * 8 + lane * 2 + q;
        atomicAdd(&g_pos[jb_prev * TN + col], cp * INV_T);
        atomicAdd(&g_se[jb_prev * TN + col],  ce);
    }
}

// GEMM with software-pipelined fragment loads; optionally interleaves previous-tile epilogue.
template <bool FUSE>
__device__ __forceinline__ void gemm_tile(
    uint32_t aBase, uint32_t bBase, int lane,
    uint32_t c[2][4][2],
    const uint32_t cprev[2][4][2], const int* lb_prev, const int lab_row[4],
    float pos[4], float se[4], int jb_prev, int wn)
{
#pragma unroll
    for (int mt = 0; mt < 2; mt++)
#pragma unroll
        for (int nt = 0; nt < 4; nt++) { c[mt][nt][0] = 0u; c[mt][nt][1] = 0u; }

    const int rsel = (lane & 15);
    const int koff = ((lane >> 4) << 3) * 2;

    uint32_t a[2][2][4], b[2][2][4];   // [buf][frag][reg]
    {
        int kb = koff;
        LDSM_X4(a[0][0][0], a[0][0][1], a[0][0][2], a[0][0][3], aBase + rsel * ROW_B + kb);
        LDSM_X4(a[0][1][0], a[0][1][1], a[0][1][2], a[0][1][3], aBase + (16 + rsel) * ROW_B + kb);
        LDSM_X4(b[0][0][0], b[0][0][1], b[0][0][2], b[0][0][3], bBase + rsel * ROW_B + kb);
        LDSM_X4(b[0][1][0], b[0][1][1], b[0][1][2], b[0][1][3], bBase + (16 + rsel) * ROW_B + kb);
    }

#pragma unroll
    for (int kk = 0; kk < 16; kk++) {
        int cur = kk & 1, nxt = cur ^ 1;
        if (kk < 15) {
            int kb = (kk + 1) * 32 + koff;
            LDSM_X4(a[nxt][0][0], a[nxt][0][1], a[nxt][0][2], a[nxt][0][3], aBase + rsel * ROW_B + kb);
            LDSM_X4(a[nxt][1][0], a[nxt][1][1], a[nxt][1][2], a[nxt][1][3], aBase + (16 + rsel) * ROW_B + kb);
            LDSM_X4(b[nxt][0][0], b[nxt][0][1], b[nxt][0][2], b[nxt][0][3], bBase + rsel * ROW_B + kb);
            LDSM_X4(b[nxt][1][0], b[nxt][1][1], b[nxt][1][2], b[nxt][1][3], bBase + (16 + rsel) * ROW_B + kb);
        }
#pragma unroll
        for (int mt = 0; mt < 2; mt++)
#pragma unroll
            for (int nt = 0; nt < 4; nt++)
                MMA16816F16(c[mt][nt], a[cur][mt],
                            b[cur][nt >> 1][nt & 1], b[cur][nt >> 1][2 + (nt & 1)]);

        if (FUSE && (kk & 1))
            epi_group(kk >> 1, cprev, lb_prev, lab_row, pos, se, jb_prev, wn, lane);
    }
}

__global__ void __launch_bounds__(512, 1) k_sim() {
    extern __shared__ char smem[];
    uint32_t su = smem_to_u32(smem);
    int* labs = reinterpret_cast<int*>(smem);     // [3][128] triple-buffered labels

    int tid  = threadIdx.x;
    int lane = tid & 31;
    int wid  = tid >> 5;                 // 0..15
    const int wm = (wid >> 2) * 32;      // warp m-offset
    const int wn = (wid & 3) * 32;       // warp n-offset
    const int g  = lane >> 2;
    const int t4 = lane & 3;

    int w0 = (blockIdx.x * TOTW) / NCTA;
    int w1 = ((blockIdx.x + 1) * TOTW) / NCTA;
    int ib, d, sw;
    locate_w(w0, ib, d, sw);
    if (ib >= 64 || sw >= w1) return;

    // pre-loop: prefetch first tile's B + labels into buf 0 / slot 0
    {
        int jb0 = (ib + d) & 63;
        if (d != 0) cpasync_tile(su + OFF_B0, g_Z + (size_t)jb0 * TN * DIM, tid);
        CP_COMMIT();
        if (tid < 128) labs[tid] = g_lab[jb0 * TN + tid];
    }
    int buf = 0, slot = 0;

    int cur_ib = -1;
    int lab_row[4], row_g[4];
    float pos[4], se[4];

    bool     pending = false;
    uint32_t cprev[2][4][2];
    int      jb_prev = 0, slot_prev = 0;
    uint32_t c[2][4][2];

    while (true) {
        int jb = (ib + d) & 63;

        if (ib != cur_ib) {
            if (pending) {
#pragma unroll
                for (int ci = 0; ci < 8; ci++)
                    epi_group(ci, cprev, labs + slot_prev * 128, lab_row, pos, se, jb_prev, wn, lane);
                pending = false;
            }
            if (cur_ib >= 0) {
#pragma unroll
                for (int s = 0; s < 4; s++) {
                    float p = pos[s], e = se[s];
                    p += __shfl_xor_sync(0xffffffffu, p, 1);
                    p += __shfl_xor_sync(0xffffffffu, p, 2);
                    e += __shfl_xor_sync(0xffffffffu, e, 1);
                    e += __shfl_xor_sync(0xffffffffu, e, 2);
                    if (t4 == 0) {
                        atomicAdd(&g_pos[row_g[s]], p * INV_T);
                        atomicAdd(&g_se[row_g[s]],  e);
                    }
                }
            }
            cpasync_tile(su + OFF_A, g_Z + (size_t)ib * TM * DIM, tid);
            CP_COMMIT();
            CP_WAIT0();            // also drains any in-flight B prefetch
            __syncthreads();
            cur_ib = ib;
#pragma unroll
            for (int s = 0; s < 4; s++) {
                int mt = s >> 1, h = s & 1;
                row_g[s]   = ib * TM + wm + mt * 16 + g + 8 * h;
                lab_row[s] = g_lab[row_g[s]];
                pos[s] = 0.f;  se[s] = 0.f;
            }
        }

        uint32_t bbuf = (d == 0) ? (su + OFF_A) : (su + (buf ? OFF_B1 : OFF_B0));

        int swn = sw + ((d == 0) ? W_DIAG : W_OFF);
        int ibn = ib, dn = d + 1;
        if (dn > dmax_of(ib)) { ibn++; dn = 0; }
        bool has_next = (ibn < 64) && (swn < w1);
        int slot_next = (slot == 2) ? 0 : slot + 1;

        if (has_next) {
            int jn = (ibn + dn) & 63;
            if (dn != 0) cpasync_tile(su + ((buf ^ 1) ? OFF_B1 : OFF_B0),
                                      g_Z + (size_t)jn * TN * DIM, tid);
            CP_COMMIT();
            if (tid < 128) labs[slot_next * 128 + tid] = g_lab[jn * TN + tid];
        }

        uint32_t aBase = su + OFF_A + wm * ROW_B;
        uint32_t bBase = bbuf + wn * ROW_B;
        const int* lb = labs + slot * 128;

        if (d == 0) {
            gemm_tile<false>(aBase, bBase, lane, c, cprev, lb, lab_row, pos, se, jb_prev, wn);
#pragma unroll
            for (int mt = 0; mt < 2; mt++)
#pragma unroll
                for (int nt = 0; nt < 4; nt++)
#pragma unroll
                    for (int h = 0; h < 2; h++) {
                        int s = mt * 2 + h;
                        float2 f = __half22float2(*reinterpret_cast<__half2*>(&c[mt][nt][h]));
#pragma unroll
                        for (int q = 0; q < 2; q++) {
                            int coll = wn + nt * 8 + t4 * 2 + q;
                            float v  = q ? f.y : f.x;
                            if (lb[coll] == lab_row[s]) {
                                if (ib * TM + coll != row_g[s]) pos[s] += v;
                            } else {
                                se[s] += ex2f(v * K2);
                            }
                        }
                    }
        } else {
            if (pending)
                gemm_tile<true>(aBase, bBase, lane, c, cprev, labs + slot_prev * 128,
                                lab_row, pos, se, jb_prev, wn);
            else
                gemm_tile<false>(aBase, bBase, lane, c, cprev, lb, lab_row, pos, se, jb_prev, wn);

#pragma unroll
            for (int mt = 0; mt < 2; mt++)
#pragma unroll
                for (int nt = 0; nt < 4; nt++) {
                    cprev[mt][nt][0] = c[mt][nt][0];
                    cprev[mt][nt][1] = c[mt][nt][1];
                }
            jb_prev   = jb;
            slot_prev = slot;
            pending   = true;
        }

        if (!has_next) break;
        CP_WAIT0();
        __syncthreads();
        ib = ibn; d = dn; sw = swn; buf ^= 1; slot = slot_next;
    }

    if (pending) {
#pragma unroll
        for (int ci = 0; ci < 8; ci++)
            epi_group(ci, cprev, labs + slot_prev * 128, lab_row, pos, se, jb_prev, wn, lane);
    }
    if (cur_ib >= 0) {
#pragma unroll
        for (int s = 0; s < 4; s++) {
            float p = pos[s], e = se[s];
            p += __shfl_xor_sync(0xffffffffu, p, 1);
            p += __shfl_xor_sync(0xffffffffu, p, 2);
            e += __shfl_xor_sync(0xffffffffu, e, 1);
            e += __shfl_xor_sync(0xffffffffu, e, 2);
            if (t4 == 0) {
                atomicAdd(&g_pos[row_g[s]], p * INV_T);
                atomicAdd(&g_se[row_g[s]],  e);
            }
        }
    }
}

// ============================ kernel 3: final reduction (32 CTAs x 256) ============================
__global__ void k_final(float* __restrict__ out) {
    __shared__ float red[8];
    int r = blockIdx.x * 256 + threadIdx.x;
    // loss_i = logaddexp(0, lse_neg - pos_sim); |sim|<=14.3 so sum-exp is fp32-safe
    float x  = logf(g_se[r]) - g_pos[r];
    float li = (x > 0.f) ? (x + log1pf(expf(-x))) : log1pf(expf(x));
#pragma unroll
    for (int o = 16; o > 0; o >>= 1) li += __shfl_xor_sync(0xffffffffu, li, o);
    if ((threadIdx.x & 31) == 0) red[threadIdx.x >> 5] = li;
    __syncthreads();
    if (threadIdx.x < 32) {
        float a = (threadIdx.x < 8) ? red[threadIdx.x] : 0.f;
#pragma unroll
        for (int o = 4; o > 0; o >>= 1) a += __shfl_xor_sync(0xffffffffu, a, o);
        if (threadIdx.x == 0) atomicAdd(out, a * (1.0f / (float)NROWS));
    }
}

// ============================ launch ============================
extern "C" void kernel_launch(void* const* d_in, const int* in_sizes, int n_in,
                              void* d_out, int out_size) {
    (void)in_sizes; (void)n_in; (void)out_size;
    const float* zi  = (const float*)d_in[0];
    const float* zj  = (const float*)d_in[1];
    const int*   lab = (const int*)d_in[2];    // int32 or int64; auto-detected

    cudaFuncSetAttribute(k_sim, cudaFuncAttributeMaxDynamicSharedMemorySize, SMEM_BYTES);

    k_norm<<<NROWS / 16, 256>>>(zi, zj, lab, (float*)d_out);
    k_sim<<<NCTA, 512, SMEM_BYTES>>>();
    k_final<<<NROWS / 256, 256>>>((float*)d_out);
}